// round 1
// baseline (speedup 1.0000x reference)
#include <cuda_runtime.h>
#include <math.h>

// Problem constants (fixed shapes)
#define NB   4
#define CCH  256
#define NPIX 4096
#define BSTRIDE ((size_t)CCH * NPIX)   // 1048576 elements per batch per tensor

// Scratch: 16 MB each (static __device__ — allocation-free per harness rules)
__device__ float g_Q[(size_t)NB * NPIX * CCH];  // [b][n][c]
__device__ float g_K[(size_t)NB * NPIX * CCH];  // [b][c][n]
__device__ float g_V[(size_t)NB * NPIX * CCH];  // [b][n][c]
__device__ float g_R[(size_t)NB * NPIX * CCH];  // [b][c][n]

// ---------------------------------------------------------------------------
// proj_kernel: out = W @ X (+ bias), per batch.
//   X: [b][k][n]  (k = input channel, n contiguous)
//   W: [d][k]     (row-major 256x256)
//   TRANS==0: out[b][n][d]   (n-major rows, d contiguous)
//   TRANS==1: out[b][d][n]   (d-major rows, n contiguous)
// Tile 64n x 64d, 256 threads, 4x4 micro, k-chunks of 16.
// ---------------------------------------------------------------------------
template <int TRANS>
__global__ __launch_bounds__(256) void proj_kernel(
    const float* __restrict__ X, const float* __restrict__ W,
    const float* __restrict__ bias, float* __restrict__ out)
{
    __shared__ float Xs[16][68];
    __shared__ float Ws[16][68];

    const int b  = blockIdx.z;
    const int c0 = blockIdx.y * 64;
    const int n0 = blockIdx.x * 64;
    const int tid = threadIdx.x;
    const int ty = tid >> 4;     // 0..15
    const int tx = tid & 15;     // 0..15
    const size_t bX = (size_t)b * BSTRIDE;

    float acc[4][4] = {};

    for (int k0 = 0; k0 < CCH; k0 += 16) {
        __syncthreads();
        {
            // Xs[kk][n4..n4+3]  (coalesced along n)
            const int kk = tid >> 4;
            const int n4 = (tid & 15) << 2;
            *(float4*)&Xs[kk][n4] =
                *(const float4*)&X[bX + (size_t)(k0 + kk) * NPIX + n0 + n4];
            // Ws[kk][cc] from W[c][k] (coalesced along k)
            const int cc  = tid >> 2;
            const int kk4 = (tid & 3) << 2;
            float4 wv = *(const float4*)&W[(c0 + cc) * CCH + k0 + kk4];
            Ws[kk4 + 0][cc] = wv.x;
            Ws[kk4 + 1][cc] = wv.y;
            Ws[kk4 + 2][cc] = wv.z;
            Ws[kk4 + 3][cc] = wv.w;
        }
        __syncthreads();

        #pragma unroll
        for (int kk = 0; kk < 16; kk++) {
            float4 av4, wv4;
            if (TRANS) { av4 = *(float4*)&Ws[kk][ty * 4]; wv4 = *(float4*)&Xs[kk][tx * 4]; }
            else       { av4 = *(float4*)&Xs[kk][ty * 4]; wv4 = *(float4*)&Ws[kk][tx * 4]; }
            float a[4] = {av4.x, av4.y, av4.z, av4.w};
            float w[4] = {wv4.x, wv4.y, wv4.z, wv4.w};
            #pragma unroll
            for (int i = 0; i < 4; i++)
                #pragma unroll
                for (int j = 0; j < 4; j++)
                    acc[i][j] += a[i] * w[j];
        }
    }

    if (TRANS) {
        // rows = output channel (ty), cols = n (tx): out[b][d][n]
        #pragma unroll
        for (int i = 0; i < 4; i++) {
            float bb = bias[c0 + ty * 4 + i];
            float4 o = make_float4(acc[i][0] + bb, acc[i][1] + bb,
                                   acc[i][2] + bb, acc[i][3] + bb);
            *(float4*)&out[bX + (size_t)(c0 + ty * 4 + i) * NPIX + n0 + tx * 4] = o;
        }
    } else {
        // rows = n (ty), cols = output channel (tx): out[b][n][d]
        float4 bb = *(const float4*)&bias[c0 + tx * 4];
        #pragma unroll
        for (int i = 0; i < 4; i++) {
            float4 o = make_float4(acc[i][0] + bb.x, acc[i][1] + bb.y,
                                   acc[i][2] + bb.z, acc[i][3] + bb.w);
            *(float4*)&out[bX + (size_t)(n0 + ty * 4 + i) * CCH + c0 + tx * 4] = o;
        }
    }
}

// ---------------------------------------------------------------------------
// Flash attention: per CTA one (batch, 64-query tile). Loops over 64 key tiles.
//   Q: [b][n][c], K: [b][c][m], V: [b][m][c]  ->  R: [b][c][n]
// Online softmax (unscaled logits, matching reference).
// smem: Qs 64x256 | Ks 256x64 | Vs 64x256 | Ps 64x64  = 212992 B
// ---------------------------------------------------------------------------
#define FLASH_SMEM ((3 * 64 * 256 + 64 * 64) * 4)

__global__ __launch_bounds__(256, 1) void flash_kernel(
    const float* __restrict__ Qg_, const float* __restrict__ Kg_,
    const float* __restrict__ Vg_, float* __restrict__ Rg_)
{
    extern __shared__ float sm[];
    float* Qs = sm;                  // [64][256]
    float* Ks = sm + 64 * 256;       // [256][64]
    float* Vs = sm + 2 * 64 * 256;   // [64][256]
    float* Ps = sm + 3 * 64 * 256;   // [64][64]

    const int b  = blockIdx.y;
    const int n0 = blockIdx.x * 64;
    const int tid = threadIdx.x;
    const int ty = tid >> 4;   // query-row block 0..15
    const int tx = tid & 15;   // key-col / channel block 0..15

    // Load Q tile (64 x 256), coalesced float4
    const float* Qg = Qg_ + ((size_t)b * NPIX + n0) * CCH;
    for (int i = tid; i < 64 * 64; i += 256) {
        int r = i >> 6, c4 = (i & 63) << 2;
        *(float4*)&Qs[r * 256 + c4] = *(const float4*)&Qg[r * 256 + c4];
    }

    float acc[4][16];
    #pragma unroll
    for (int i = 0; i < 4; i++)
        #pragma unroll
        for (int j = 0; j < 16; j++) acc[i][j] = 0.0f;

    float mrow[4] = {-1e30f, -1e30f, -1e30f, -1e30f};
    float lrow[4] = {0.0f, 0.0f, 0.0f, 0.0f};

    const float* Kb = Kg_ + (size_t)b * BSTRIDE;

    for (int jt = 0; jt < 64; jt++) {
        __syncthreads();   // protects Ks/Vs/Ps reuse across iterations
        const int m0 = jt * 64;

        // Load K tile transposed-in-global: Ks[c][m] (coalesced along m)
        for (int i = tid; i < 256 * 16; i += 256) {
            int c = i >> 4, m4 = (i & 15) << 2;
            *(float4*)&Ks[c * 64 + m4] =
                *(const float4*)&Kb[(size_t)c * NPIX + m0 + m4];
        }
        // Load V tile: Vs[m][c] (coalesced along c)
        const float* Vg = Vg_ + ((size_t)b * NPIX + m0) * CCH;
        for (int i = tid; i < 64 * 64; i += 256) {
            int r = i >> 6, c4 = (i & 63) << 2;
            *(float4*)&Vs[r * 256 + c4] = *(const float4*)&Vg[r * 256 + c4];
        }
        __syncthreads();

        // --- S tile: s[i][j] = sum_k Qs[ty*4+i][k] * Ks[k][tx*4+j] ---
        float s[4][4] = {};
        #pragma unroll 2
        for (int k = 0; k < 256; k += 4) {
            float qr[4][4];
            #pragma unroll
            for (int i = 0; i < 4; i++) {
                float4 t = *(float4*)&Qs[(ty * 4 + i) * 256 + k];
                qr[i][0] = t.x; qr[i][1] = t.y; qr[i][2] = t.z; qr[i][3] = t.w;
            }
            #pragma unroll
            for (int kk = 0; kk < 4; kk++) {
                float4 t = *(float4*)&Ks[(k + kk) * 64 + tx * 4];
                #pragma unroll
                for (int i = 0; i < 4; i++) {
                    s[i][0] += qr[i][kk] * t.x;
                    s[i][1] += qr[i][kk] * t.y;
                    s[i][2] += qr[i][kk] * t.z;
                    s[i][3] += qr[i][kk] * t.w;
                }
            }
        }

        // --- online softmax over the 64 keys of this tile ---
        #pragma unroll
        for (int i = 0; i < 4; i++) {
            float mt = fmaxf(fmaxf(s[i][0], s[i][1]), fmaxf(s[i][2], s[i][3]));
            #pragma unroll
            for (int d = 8; d >= 1; d >>= 1)
                mt = fmaxf(mt, __shfl_xor_sync(0xffffffffu, mt, d));
            float mn  = fmaxf(mrow[i], mt);
            float scl = __expf(mrow[i] - mn);
            float p0 = __expf(s[i][0] - mn);
            float p1 = __expf(s[i][1] - mn);
            float p2 = __expf(s[i][2] - mn);
            float p3 = __expf(s[i][3] - mn);
            float lt = p0 + p1 + p2 + p3;
            #pragma unroll
            for (int d = 8; d >= 1; d >>= 1)
                lt += __shfl_xor_sync(0xffffffffu, lt, d);
            lrow[i] = lrow[i] * scl + lt;
            mrow[i] = mn;
            #pragma unroll
            for (int j = 0; j < 16; j++) acc[i][j] *= scl;
            *(float4*)&Ps[(ty * 4 + i) * 64 + tx * 4] = make_float4(p0, p1, p2, p3);
        }
        __syncthreads();

        // --- PV: acc[i][q*4+jj] += P[row][m] * Vs[m][q*64 + tx*4 + jj] ---
        #pragma unroll 2
        for (int m = 0; m < 64; m++) {
            float pr[4];
            #pragma unroll
            for (int i = 0; i < 4; i++) pr[i] = Ps[(ty * 4 + i) * 64 + m];
            #pragma unroll
            for (int q = 0; q < 4; q++) {
                float4 vv = *(float4*)&Vs[m * 256 + q * 64 + tx * 4];
                #pragma unroll
                for (int i = 0; i < 4; i++) {
                    acc[i][q * 4 + 0] += pr[i] * vv.x;
                    acc[i][q * 4 + 1] += pr[i] * vv.y;
                    acc[i][q * 4 + 2] += pr[i] * vv.z;
                    acc[i][q * 4 + 3] += pr[i] * vv.w;
                }
            }
        }
    }

    // --- epilogue: normalize, transpose through smem, store R[b][c][n] ---
    float inv[4];
    #pragma unroll
    for (int i = 0; i < 4; i++) inv[i] = 1.0f / lrow[i];

    __syncthreads();   // everyone done with Qs/Ks regions
    // Ot[c][n_local] with row stride 65 (bank-stagger), occupies sm[0 .. 16640)
    #pragma unroll
    for (int q = 0; q < 4; q++)
        #pragma unroll
        for (int jj = 0; jj < 4; jj++) {
            int c = q * 64 + tx * 4 + jj;
            #pragma unroll
            for (int i = 0; i < 4; i++)
                sm[c * 65 + ty * 4 + i] = acc[i][q * 4 + jj] * inv[i];
        }
    __syncthreads();

    float* Rg = Rg_ + (size_t)b * BSTRIDE + n0;
    for (int i = tid; i < 256 * 64; i += 256) {
        int c = i >> 6, n = i & 63;
        Rg[(size_t)c * NPIX + n] = sm[c * 65 + n];
    }
}

// ---------------------------------------------------------------------------
extern "C" void kernel_launch(void* const* d_in, const int* in_sizes, int n_in,
                              void* d_out, int out_size)
{
    (void)in_sizes; (void)n_in; (void)out_size;
    const float* F_c = (const float*)d_in[0];
    const float* F_s = (const float*)d_in[1];
    const float* Wf  = (const float*)d_in[2];
    const float* bf  = (const float*)d_in[3];
    const float* Wg  = (const float*)d_in[4];
    const float* bg  = (const float*)d_in[5];
    const float* Wh  = (const float*)d_in[6];
    const float* bh  = (const float*)d_in[7];
    const float* Wo  = (const float*)d_in[8];
    const float* bo  = (const float*)d_in[9];

    float *gQ, *gK, *gV, *gR;
    cudaGetSymbolAddress((void**)&gQ, g_Q);
    cudaGetSymbolAddress((void**)&gK, g_K);
    cudaGetSymbolAddress((void**)&gV, g_V);
    cudaGetSymbolAddress((void**)&gR, g_R);

    cudaFuncSetAttribute(flash_kernel,
                         cudaFuncAttributeMaxDynamicSharedMemorySize, FLASH_SMEM);

    dim3 pg(64, 4, 4);   // n-tiles, c-tiles, batch
    proj_kernel<0><<<pg, 256>>>(F_c, Wf, bf, gQ);   // Q: [b][n][c]
    proj_kernel<1><<<pg, 256>>>(F_s, Wg, bg, gK);   // K: [b][c][n]
    proj_kernel<0><<<pg, 256>>>(F_s, Wh, bh, gV);   // V: [b][n][c]

    flash_kernel<<<dim3(64, NB), 256, FLASH_SMEM>>>(gQ, gK, gV, gR);

    proj_kernel<1><<<pg, 256>>>(gR, Wo, bo, (float*)d_out);  // out: [b][d][n]
}

// round 5
// speedup vs baseline: 4.6491x; 4.6491x over previous
#include <cuda_runtime.h>
#include <cuda_bf16.h>
#include <stdint.h>
#include <math.h>

#define NB   4
#define CCH  256
#define NPIX 4096
#define BSTRIDE ((size_t)CCH * NPIX)

// ---------------- scratch (static __device__, allocation-free) --------------
__device__ __align__(1024) __nv_bfloat16 g_Qh[(size_t)NB * NPIX * CCH];
__device__ __align__(1024) __nv_bfloat16 g_Ql[(size_t)NB * NPIX * CCH];
__device__ __align__(1024) __nv_bfloat16 g_Kh[(size_t)NB * NPIX * CCH];
__device__ __align__(1024) __nv_bfloat16 g_Kl[(size_t)NB * NPIX * CCH];
__device__ __align__(1024) __nv_bfloat16 g_Vh[(size_t)NB * CCH * NPIX];
__device__ __align__(1024) __nv_bfloat16 g_Vl[(size_t)NB * CCH * NPIX];
__device__ __align__(1024) float         g_S [(size_t)NB * NPIX * NPIX];   // 256 MB, reused for P
__device__ __align__(1024) float         g_R [(size_t)NB * CCH * NPIX];    // 16 MB

// ---------------- portable PTX helpers (NO sm_10xa features) ----------------
__device__ __forceinline__ uint32_t smem_u32(const void* p) {
    uint32_t a;
    asm("{ .reg .u64 t; cvta.to.shared.u64 t, %1; cvt.u32.u64 %0, t; }"
        : "=r"(a) : "l"(p));
    return a;
}
__device__ __forceinline__ void cpa16(uint32_t dst, const void* src) {
    asm volatile("cp.async.cg.shared.global [%0], [%1], 16;"
                 :: "r"(dst), "l"(src));
}
__device__ __forceinline__ void cpa_commit() {
    asm volatile("cp.async.commit_group;" ::: "memory");
}
template <int N> __device__ __forceinline__ void cpa_wait() {
    asm volatile("cp.async.wait_group %0;" :: "n"(N) : "memory");
}
__device__ __forceinline__ void ldsm4(uint32_t* r, uint32_t a) {
    asm volatile("ldmatrix.sync.aligned.m8n8.x4.shared.b16 {%0,%1,%2,%3}, [%4];"
                 : "=r"(r[0]), "=r"(r[1]), "=r"(r[2]), "=r"(r[3]) : "r"(a));
}
__device__ __forceinline__ void mma16816(float* d, const uint32_t* a, const uint32_t* b) {
    asm volatile("mma.sync.aligned.m16n8k16.row.col.f32.bf16.bf16.f32 "
                 "{%0,%1,%2,%3}, {%4,%5,%6,%7}, {%8,%9}, {%0,%1,%2,%3};"
                 : "+f"(d[0]), "+f"(d[1]), "+f"(d[2]), "+f"(d[3])
                 : "r"(a[0]), "r"(a[1]), "r"(a[2]), "r"(a[3]),
                   "r"(b[0]), "r"(b[1]));
}
__device__ __forceinline__ uint32_t swz(uint32_t off) {       // SW128
    return off ^ ((off >> 3) & 0x70);
}
__device__ __forceinline__ unsigned pk2(float a, float b) {
    __nv_bfloat162 t = __floats2bfloat162_rn(a, b);
    return *reinterpret_cast<unsigned*>(&t);
}
__device__ __forceinline__ void split1(float v, float& h, float& l) {
    __nv_bfloat16 hb = __float2bfloat16_rn(v);
    h = __bfloat162float(hb);
    l = v - h;
}

// ---------------- fp32 SIMT projection (proven in R1) -----------------------
__global__ __launch_bounds__(256) void proj_kernel(
    const float* __restrict__ X, const float* __restrict__ W,
    const float* __restrict__ bias, float* __restrict__ out)
{
    __shared__ float Xs[16][68];
    __shared__ float Ws[16][68];
    const int b  = blockIdx.z;
    const int c0 = blockIdx.y * 64;
    const int n0 = blockIdx.x * 64;
    const int tid = threadIdx.x;
    const int ty = tid >> 4, tx = tid & 15;
    const size_t bX = (size_t)b * BSTRIDE;
    float acc[4][4] = {};

    for (int k0 = 0; k0 < CCH; k0 += 16) {
        __syncthreads();
        {
            const int kk = tid >> 4, n4 = (tid & 15) << 2;
            *(float4*)&Xs[kk][n4] =
                *(const float4*)&X[bX + (size_t)(k0 + kk) * NPIX + n0 + n4];
            const int cc = tid >> 2, kk4 = (tid & 3) << 2;
            float4 wv = *(const float4*)&W[(c0 + cc) * CCH + k0 + kk4];
            Ws[kk4 + 0][cc] = wv.x; Ws[kk4 + 1][cc] = wv.y;
            Ws[kk4 + 2][cc] = wv.z; Ws[kk4 + 3][cc] = wv.w;
        }
        __syncthreads();
        #pragma unroll
        for (int kk = 0; kk < 16; kk++) {
            float4 av4 = *(float4*)&Ws[kk][ty * 4];
            float4 wv4 = *(float4*)&Xs[kk][tx * 4];
            float a[4] = {av4.x, av4.y, av4.z, av4.w};
            float w[4] = {wv4.x, wv4.y, wv4.z, wv4.w};
            #pragma unroll
            for (int i = 0; i < 4; i++)
                #pragma unroll
                for (int j = 0; j < 4; j++) acc[i][j] += a[i] * w[j];
        }
    }
    #pragma unroll
    for (int i = 0; i < 4; i++) {
        float bb = bias[c0 + ty * 4 + i];
        float4 o = make_float4(acc[i][0] + bb, acc[i][1] + bb,
                               acc[i][2] + bb, acc[i][3] + bb);
        *(float4*)&out[bX + (size_t)(c0 + ty * 4 + i) * NPIX + n0 + tx * 4] = o;
    }
}

// ---------------- projection with split-bf16 output -------------------------
template <int TRANS>
__global__ __launch_bounds__(256) void proj_split(
    const float* __restrict__ X, const float* __restrict__ W,
    const float* __restrict__ bias,
    __nv_bfloat16* __restrict__ Oh, __nv_bfloat16* __restrict__ Ol)
{
    __shared__ float Xs[16][68];
    __shared__ float Ws[16][68];
    const int b  = blockIdx.z;
    const int c0 = blockIdx.y * 64;
    const int n0 = blockIdx.x * 64;
    const int tid = threadIdx.x;
    const int ty = tid >> 4, tx = tid & 15;
    const size_t bX = (size_t)b * BSTRIDE;
    float acc[4][4] = {};

    for (int k0 = 0; k0 < CCH; k0 += 16) {
        __syncthreads();
        {
            const int kk = tid >> 4, n4 = (tid & 15) << 2;
            *(float4*)&Xs[kk][n4] =
                *(const float4*)&X[bX + (size_t)(k0 + kk) * NPIX + n0 + n4];
            const int cc = tid >> 2, kk4 = (tid & 3) << 2;
            float4 wv = *(const float4*)&W[(c0 + cc) * CCH + k0 + kk4];
            Ws[kk4 + 0][cc] = wv.x; Ws[kk4 + 1][cc] = wv.y;
            Ws[kk4 + 2][cc] = wv.z; Ws[kk4 + 3][cc] = wv.w;
        }
        __syncthreads();
        #pragma unroll
        for (int kk = 0; kk < 16; kk++) {
            float4 av4, wv4;
            if (TRANS) { av4 = *(float4*)&Ws[kk][ty * 4]; wv4 = *(float4*)&Xs[kk][tx * 4]; }
            else       { av4 = *(float4*)&Xs[kk][ty * 4]; wv4 = *(float4*)&Ws[kk][tx * 4]; }
            float a[4] = {av4.x, av4.y, av4.z, av4.w};
            float w[4] = {wv4.x, wv4.y, wv4.z, wv4.w};
            #pragma unroll
            for (int i = 0; i < 4; i++)
                #pragma unroll
                for (int j = 0; j < 4; j++) acc[i][j] += a[i] * w[j];
        }
    }

    #pragma unroll
    for (int i = 0; i < 4; i++) {
        float v[4], h[4], l[4];
        size_t idx;
        if (TRANS) {
            float bb = bias[c0 + ty * 4 + i];
            #pragma unroll
            for (int j = 0; j < 4; j++) v[j] = acc[i][j] + bb;
            idx = bX + (size_t)(c0 + ty * 4 + i) * NPIX + n0 + tx * 4;
        } else {
            #pragma unroll
            for (int j = 0; j < 4; j++) v[j] = acc[i][j] + bias[c0 + tx * 4 + j];
            idx = bX + (size_t)(n0 + ty * 4 + i) * CCH + c0 + tx * 4;
        }
        #pragma unroll
        for (int j = 0; j < 4; j++) split1(v[j], h[j], l[j]);
        uint2 uh; uh.x = pk2(h[0], h[1]); uh.y = pk2(h[2], h[3]);
        uint2 ul; ul.x = pk2(l[0], l[1]); ul.y = pk2(l[2], l[3]);
        *(uint2*)&Oh[idx] = uh;
        *(uint2*)&Ol[idx] = ul;
    }
}

// ---------------- mma.sync split-bf16 GEMM: D[i][j] = sum_k A[i][k]*B[j][k] -
// CTA 128(M) x 128(N), K-chunk 64, 8 warps as 4(m) x 2(n), warp tile 32x64.
// smem/stage: Ah 16K | Al 16K | Bh 16K | Bl 16K = 64 KB; 2 stages = 128 KB.
#define GS_STAGE 65536
#define GSMEM (2 * GS_STAGE)

__global__ __launch_bounds__(256, 1) void gemm_mma(
    const __nv_bfloat16* __restrict__ Ah_, const __nv_bfloat16* __restrict__ Al_,
    const __nv_bfloat16* __restrict__ Bh_, const __nv_bfloat16* __restrict__ Bl_,
    float* __restrict__ D_,
    int K, int lda, int ldb, int ldd,
    size_t strA, size_t strB, size_t strD)
{
    extern __shared__ char smdyn[];
    const uint32_t sb = smem_u32(smdyn);
    const int tid  = threadIdx.x;
    const int wid  = tid >> 5;
    const int lane = tid & 31;
    const int m0 = blockIdx.x * 128;
    const int n0 = blockIdx.y * 128;
    const int b  = blockIdx.z;

    const __nv_bfloat16* Agh = Ah_ + (size_t)b * strA;
    const __nv_bfloat16* Agl = Al_ + (size_t)b * strA;
    const __nv_bfloat16* Bgh = Bh_ + (size_t)b * strB;
    const __nv_bfloat16* Bgl = Bl_ + (size_t)b * strB;

    const int nk = K >> 6;

    auto load_chunk = [&](int kc, int stg) {
        const int k0 = kc << 6;
        const uint32_t st = sb + stg * GS_STAGE;
        #pragma unroll
        for (int u = tid; u < 1024; u += 256) {          // A: 128 rows x 8 x 16B
            const int row = u >> 3, c = u & 7;
            const uint32_t off = swz((uint32_t)(row * 128 + c * 16));
            const size_t g = (size_t)(m0 + row) * lda + k0 + c * 8;
            cpa16(st + off,         Agh + g);
            cpa16(st + 16384 + off, Agl + g);
        }
        #pragma unroll
        for (int u = tid; u < 1024; u += 256) {          // B: 128 rows x 8 x 16B
            const int row = u >> 3, c = u & 7;
            const uint32_t off = swz((uint32_t)(row * 128 + c * 16));
            const size_t g = (size_t)(n0 + row) * ldb + k0 + c * 8;
            cpa16(st + 32768 + off, Bgh + g);
            cpa16(st + 49152 + off, Bgl + g);
        }
        cpa_commit();
    };

    float acc[2][8][4];
    #pragma unroll
    for (int i = 0; i < 2; i++)
        #pragma unroll
        for (int j = 0; j < 8; j++)
            #pragma unroll
            for (int q = 0; q < 4; q++) acc[i][j][q] = 0.0f;

    const int wm = (wid & 3) * 32;
    const int wn = (wid >> 2) * 64;

    load_chunk(0, 0);

    for (int kc = 0; kc < nk; kc++) {
        const int s = kc & 1;
        if (kc + 1 < nk) { load_chunk(kc + 1, s ^ 1); cpa_wait<1>(); }
        else             { cpa_wait<0>(); }
        __syncthreads();

        const uint32_t st = sb + s * GS_STAGE;
        #pragma unroll
        for (int ks = 0; ks < 4; ks++) {
            // A fragments (2 m16 tiles, h & l)
            uint32_t a_h[2][4], a_l[2][4];
            #pragma unroll
            for (int mi = 0; mi < 2; mi++) {
                const int row  = wm + mi * 16 + (lane & 15);
                const int colb = ks * 32 + ((lane >> 4) << 4);
                const uint32_t ad = st + swz((uint32_t)(row * 128 + colb));
                ldsm4(a_h[mi], ad);
                ldsm4(a_l[mi], ad + 16384);
            }
            // B fragments (8 n8 tiles via 4 x ldmatrix.x4, h & l)
            uint32_t b_h[8][2], b_l[8][2];
            #pragma unroll
            for (int nq = 0; nq < 4; nq++) {
                const int row  = wn + nq * 16 + (lane & 7) + ((lane >> 4) << 3);
                const int colb = ks * 32 + (((lane >> 3) & 1) << 4);
                const uint32_t bd = st + 32768 + swz((uint32_t)(row * 128 + colb));
                uint32_t r[4];
                ldsm4(r, bd);
                b_h[nq * 2][0] = r[0]; b_h[nq * 2][1] = r[1];
                b_h[nq * 2 + 1][0] = r[2]; b_h[nq * 2 + 1][1] = r[3];
                ldsm4(r, bd + 16384);
                b_l[nq * 2][0] = r[0]; b_l[nq * 2][1] = r[1];
                b_l[nq * 2 + 1][0] = r[2]; b_l[nq * 2 + 1][1] = r[3];
            }
            // 3-term split MMA
            #pragma unroll
            for (int mi = 0; mi < 2; mi++)
                #pragma unroll
                for (int nj = 0; nj < 8; nj++) {
                    mma16816(acc[mi][nj], a_h[mi], b_h[nj]);
                    mma16816(acc[mi][nj], a_h[mi], b_l[nj]);
                    mma16816(acc[mi][nj], a_l[mi], b_h[nj]);
                }
        }
        __syncthreads();   // compute done before next iteration reloads stage s
    }

    // epilogue: direct fp32 stores (float2 per fragment half)
    float* Db = D_ + (size_t)b * strD;
    #pragma unroll
    for (int mi = 0; mi < 2; mi++) {
        const int r0 = m0 + wm + mi * 16 + (lane >> 2);
        #pragma unroll
        for (int nj = 0; nj < 8; nj++) {
            const int c0v = n0 + wn + nj * 8 + (lane & 3) * 2;
            *(float2*)&Db[(size_t)r0 * ldd + c0v] =
                make_float2(acc[mi][nj][0], acc[mi][nj][1]);
            *(float2*)&Db[(size_t)(r0 + 8) * ldd + c0v] =
                make_float2(acc[mi][nj][2], acc[mi][nj][3]);
        }
    }
}

// ---------------- row softmax IN PLACE: fp32 S row -> [Ph row | Pl row] -----
__global__ __launch_bounds__(256) void softmax_kernel(float* __restrict__ S)
{
    __shared__ float red[8];
    const int row = blockIdx.x, b = blockIdx.y;
    const int tid = threadIdx.x;
    float* Sr = S + ((size_t)b * NPIX + row) * NPIX;

    float4 v[4];
    float mx = -1e30f;
    #pragma unroll
    for (int it = 0; it < 4; it++) {
        v[it] = *(const float4*)&Sr[(it * 256 + tid) * 4];
        mx = fmaxf(mx, fmaxf(fmaxf(v[it].x, v[it].y), fmaxf(v[it].z, v[it].w)));
    }
    #pragma unroll
    for (int d = 16; d >= 1; d >>= 1)
        mx = fmaxf(mx, __shfl_xor_sync(0xffffffffu, mx, d));
    if ((tid & 31) == 0) red[tid >> 5] = mx;
    __syncthreads();
    float m = red[0];
    #pragma unroll
    for (int i = 1; i < 8; i++) m = fmaxf(m, red[i]);
    __syncthreads();

    float s = 0.0f;
    #pragma unroll
    for (int it = 0; it < 4; it++) {
        v[it].x = __expf(v[it].x - m); v[it].y = __expf(v[it].y - m);
        v[it].z = __expf(v[it].z - m); v[it].w = __expf(v[it].w - m);
        s += v[it].x + v[it].y + v[it].z + v[it].w;
    }
    #pragma unroll
    for (int d = 16; d >= 1; d >>= 1)
        s += __shfl_xor_sync(0xffffffffu, s, d);
    if ((tid & 31) == 0) red[tid >> 5] = s;
    __syncthreads();
    float tot = 0.0f;
    #pragma unroll
    for (int i = 0; i < 8; i++) tot += red[i];
    const float inv = 1.0f / tot;

    __nv_bfloat16* Pr = reinterpret_cast<__nv_bfloat16*>(Sr);  // in-place
    #pragma unroll
    for (int it = 0; it < 4; it++) {
        float p[4] = {v[it].x * inv, v[it].y * inv, v[it].z * inv, v[it].w * inv};
        float h[4], l[4];
        #pragma unroll
        for (int j = 0; j < 4; j++) split1(p[j], h[j], l[j]);
        uint2 uh; uh.x = pk2(h[0], h[1]); uh.y = pk2(h[2], h[3]);
        uint2 ul; ul.x = pk2(l[0], l[1]); ul.y = pk2(l[2], l[3]);
        const int e = (it * 256 + tid) * 4;
        *(uint2*)&Pr[e]        = uh;   // Ph: first 8KB of row
        *(uint2*)&Pr[NPIX + e] = ul;   // Pl: second 8KB of row
    }
}

// ---------------------------------------------------------------------------
extern "C" void kernel_launch(void* const* d_in, const int* in_sizes, int n_in,
                              void* d_out, int out_size)
{
    (void)in_sizes; (void)n_in; (void)out_size;
    const float* F_c = (const float*)d_in[0];
    const float* F_s = (const float*)d_in[1];
    const float* Wf  = (const float*)d_in[2];
    const float* bf  = (const float*)d_in[3];
    const float* Wg  = (const float*)d_in[4];
    const float* bg  = (const float*)d_in[5];
    const float* Wh  = (const float*)d_in[6];
    const float* bh  = (const float*)d_in[7];
    const float* Wo  = (const float*)d_in[8];
    const float* bo  = (const float*)d_in[9];

    __nv_bfloat16 *gQh, *gQl, *gKh, *gKl, *gVh, *gVl;
    float *gS, *gR;
    cudaGetSymbolAddress((void**)&gQh, g_Qh);
    cudaGetSymbolAddress((void**)&gQl, g_Ql);
    cudaGetSymbolAddress((void**)&gKh, g_Kh);
    cudaGetSymbolAddress((void**)&gKl, g_Kl);
    cudaGetSymbolAddress((void**)&gVh, g_Vh);
    cudaGetSymbolAddress((void**)&gVl, g_Vl);
    cudaGetSymbolAddress((void**)&gS,  g_S);
    cudaGetSymbolAddress((void**)&gR,  g_R);

    cudaFuncSetAttribute(gemm_mma,
                         cudaFuncAttributeMaxDynamicSharedMemorySize, GSMEM);

    dim3 pg(64, 4, 4);
    // Q = Wf@F_c -> [b][n][c] split   (GEMM1 A)
    proj_split<0><<<pg, 256>>>(F_c, Wf, bf, gQh, gQl);
    // K = Wg@F_s -> [b][m][c] split   (GEMM1 B)
    proj_split<0><<<pg, 256>>>(F_s, Wg, bg, gKh, gKl);
    // V = Wh@F_s -> [b][c][m] split   (GEMM2 A)
    proj_split<1><<<pg, 256>>>(F_s, Wh, bh, gVh, gVl);

    // S[b][n][m] = sum_c Q[n][c] K[m][c]   (fp32 into g_S)
    gemm_mma<<<dim3(32, 32, NB), 256, GSMEM>>>(
        gQh, gQl, gKh, gKl, gS,
        CCH, CCH, CCH, NPIX,
        (size_t)NPIX * CCH, (size_t)NPIX * CCH, (size_t)NPIX * NPIX);

    // softmax over m, rewrite each S row in place as split-bf16 [Ph | Pl]
    softmax_kernel<<<dim3(NPIX, NB), 256>>>(gS);

    // R[b][c][n] = sum_m V[c][m] P[n][m]
    gemm_mma<<<dim3(2, 32, NB), 256, GSMEM>>>(
        gVh, gVl,
        (const __nv_bfloat16*)gS, (const __nv_bfloat16*)gS + NPIX, gR,
        NPIX, NPIX, 2 * NPIX, NPIX,
        (size_t)CCH * NPIX, (size_t)2 * NPIX * NPIX, (size_t)CCH * NPIX);

    // out = Wo@R + bo  -> [b][d][n]
    proj_kernel<<<pg, 256>>>(gR, Wo, bo, (float*)d_out);
}